// round 14
// baseline (speedup 1.0000x reference)
#include <cuda_runtime.h>
#include <stdint.h>

#define NMAX 33600
#define GMAX 128
#define CMAX 80
#define TPB 256
#define TK 10
#define GTILE 16
#define SPLIT 8
#define NW (TPB / 32)
#define CAP 768
#define TOTK (SPLIT * TK)               // 80 partial keys per gt per list
#define EPSF 1e-7f
#define INF_F 100000.0f
#define BIG_F 100000000.0f
#define CRAD 2.5f
#define NWORDS ((NMAX + 31) / 32)
#define FULLM 0xffffffffu

typedef unsigned long long ull;

// ---- scratch as __device__ globals (allocation-free rule) ----
__device__ float    g_D[(size_t)CMAX * NMAX];    // fallback path only
__device__ float    g_sumL1[NMAX];               // fallback path only
__device__ float4   g_ic4[(size_t)GMAX * NMAX / 2];   // {iou,cost} pairs, 16B-aligned
#define G_IC ((float2*)g_ic4)
__device__ unsigned g_valid[NWORDS];
__device__ int      g_cnt[NMAX];
__device__ int      g_mg[NMAX];
__device__ ull      g_amin[NMAX];                // row argmin: (fkey(cost)<<32)|g
__device__ int      g_done[GMAX];
__device__ ull      g_piou [GMAX * TOTK];
__device__ ull      g_pcost[GMAX * TOTK];

// monotone float->uint (ascending order preserved)
__device__ __forceinline__ unsigned fkey(float f) {
    unsigned u = __float_as_uint(f);
    return (u & 0x80000000u) ? ~u : (u | 0x80000000u);
}
__device__ __forceinline__ float unfkey(unsigned k) {
    unsigned u = (k & 0x80000000u) ? (k ^ 0x80000000u) : ~k;
    return __uint_as_float(u);
}

__device__ __forceinline__ ull umin64(ull a, ull b) { return a < b ? a : b; }

// ============ kAB: fused logits + pairwise (C==80), 64-anchor tiles =========
// Block = 256 threads, 64 anchors. Thread (a = tid&63, q = tid>>6) covers
// anchor a x GT-quarter q. Logit matrix in smem (stride 65, conflict-free).
// g_amin / g_valid are plain stores (full row visible in-block).
__global__ void __launch_bounds__(256) kAB(
    const float* __restrict__ ps, const float* __restrict__ priors,
    const float* __restrict__ dec, const float* __restrict__ gtb,
    const int* __restrict__ gtl, int N, int G)
{
    __shared__ float    sD[80 * 65];      // [c][a], stride 65 (conflict-free)
    __shared__ float    sPart[4 * 64];    // per-quarter partial sumL1
    __shared__ float4   sg0[GMAX];
    __shared__ float4   sg1[GMAX];
    __shared__ ull      skm[256];
    __shared__ unsigned sb[8];

    int tid = threadIdx.x;
    int n0 = blockIdx.x * 64;
    int rows = min(64, N - n0);

    // fused setup
    if (tid < rows) { g_cnt[n0 + tid] = 0; g_mg[n0 + tid] = 0x7fffffff; }
    if (blockIdx.x == 0 && tid < GMAX) g_done[tid] = 0;

    // gt descriptors (label pre-scaled by smem row stride 65)
    if (tid < G) {
        int g = tid;
        float x0 = gtb[4*g+0], y0 = gtb[4*g+1], x1 = gtb[4*g+2], y1 = gtb[4*g+3];
        sg0[g] = make_float4(x0, y0, x1, y1);
        float gcx = (x0 + x1) * 0.5f, gcy = (y0 + y1) * 0.5f;
        float area = fmaxf(x1 - x0, 0.f) * fmaxf(y1 - y0, 0.f);
        sg1[g] = make_float4(gcx, gcy, area, __int_as_float(gtl[g] * 65));
    }

    // stage ps coalesced into sD (as raw p); +65 stride => +1 bank per i
    for (int i = tid; i < rows * 80; i += 256) {
        int a = i / 80, c = i - a * 80;
        sD[c * 65 + a] = ps[n0 * 80 + i];
    }
    __syncthreads();

    int a = tid & 63, q = tid >> 6;

    // phase 1: logits in place + grouped-product partial sumL1 (4 groups of 5)
    if (a < rows) {
        float gl = 0.f;
        #pragma unroll
        for (int k2 = 0; k2 < 4; k2++) {
            float prod = 1.f;
            #pragma unroll
            for (int m = 0; m < 5; m++) {
                int c = q * 20 + k2 * 5 + m;
                float p = sD[c * 65 + a];
                float qq = 1.f - p;
                prod *= qq;
                sD[c * 65 + a] = __logf(__fdividef(p, qq));
            }
            gl += __logf(prod);
        }
        sPart[q * 64 + a] = gl;
    }
    __syncthreads();

    // phase 2: pairwise over this thread's GT quarter
    int n = n0 + a;
    bool vacc = false;
    ull kmin = ~0ULL;
    int quarter = (G + 3) >> 2;
    int gs = q * quarter;
    int ge = min(G, gs + quarter);
    if (a < rows) {
        float4 pq = ((const float4*)priors)[n];
        float px = pq.x, py = pq.y;
        float a1 = px + CRAD * pq.z, a2 = px - CRAD * pq.z;
        float b1 = py + CRAD * pq.w, b2 = py - CRAD * pq.w;
        float4 dq = ((const float4*)dec)[n];
        float dx0 = dq.x, dy0 = dq.y, dx1 = dq.z, dy1 = dq.w;
        float aa = fmaxf(dx1 - dx0, 0.f) * fmaxf(dy1 - dy0, 0.f);
        float sL1 = sPart[a] + sPart[64 + a] + sPart[128 + a] + sPart[192 + a];
        int base = gs * N + n;
        #pragma unroll 4
        for (int g = gs; g < ge; g++) {
            float4 q0 = sg0[g];
            float4 q1 = sg1[g];
            float m1 = fminf(fminf(px - q0.x, py - q0.y), fminf(q0.z - px, q0.w - py));
            float m2 = fminf(fminf(a1 - q1.x, b1 - q1.y), fminf(q1.x - a2, q1.y - b2));
            bool ing = m1 > 0.f, inc = m2 > 0.f;
            vacc = vacc || ing || inc;
            float w = fmaxf(fminf(dx1, q0.z) - fmaxf(dx0, q0.x), 0.f);
            float hh = fmaxf(fminf(dy1, q0.w) - fmaxf(dy0, q0.y), 0.f);
            float inter = w * hh;
            float uni = fmaxf(aa + q1.z - inter, EPSF);
            float iou = __fdividef(inter, uni);
            float cls = -sD[__float_as_int(q1.w) + a] - sL1;
            float cost = cls - 3.0f * __logf(iou + EPSF);
            if (!(ing && inc)) cost += INF_F;
            G_IC[base] = make_float2(iou, cost);
            base += N;
            kmin = umin64(kmin, ((ull)fkey(cost) << 32) | (unsigned)g);
        }
    }
    skm[tid] = kmin;
    unsigned bal = __ballot_sync(FULLM, vacc);
    if ((tid & 31) == 0) sb[tid >> 5] = bal;
    __syncthreads();
    if (tid < 64 && tid < rows) {
        ull m = umin64(umin64(skm[tid], skm[tid + 64]),
                       umin64(skm[tid + 128], skm[tid + 192]));
        g_amin[n0 + tid] = m;
    }
    // valid word for anchors [w32*32, w32*32+31]: warps {w32, w32+2, w32+4, w32+6}
    if (tid < 2 && tid * 32 < rows)
        g_valid[(n0 >> 5) + tid] = sb[tid] | sb[tid + 2] | sb[tid + 4] | sb[tid + 6];
}

// -------- generic fallbacks (C != 80; not used for this problem's shapes) ----
__global__ void kSetup(int N, int G) {
    int i = blockIdx.x * blockDim.x + threadIdx.x;
    if (i < N) { g_cnt[i] = 0; g_mg[i] = 0x7fffffff; g_amin[i] = ~0ULL; }
    if (i < NWORDS) g_valid[i] = 0u;
    if (i < GMAX) g_done[i] = 0;
}
__global__ void kAgen(const float* __restrict__ ps, int N, int C) {
    int n = blockIdx.x * blockDim.x + threadIdx.x;
    if (n >= N) return;
    float ssum = 0.f;
    for (int c = 0; c < C; c++) {
        float p = ps[(size_t)n * C + c];
        float L  = fmaxf(__logf(p), -100.f);
        float L1 = fmaxf(__logf(1.f - p), -100.f);
        g_D[c * N + n] = L - L1;
        ssum += L1;
    }
    g_sumL1[n] = ssum;
}
__global__ void __launch_bounds__(TPB) kB(
    const float* __restrict__ priors, const float* __restrict__ dec,
    const float* __restrict__ gtb, const int* __restrict__ gtl,
    int N, int G)
{
    __shared__ float4 sg0[GTILE];
    __shared__ float4 sg1[GTILE];
    int tid = threadIdx.x;
    int g0 = blockIdx.y * GTILE;
    int gcnt = min(GTILE, G - g0);
    if (tid < gcnt) {
        int g = g0 + tid;
        float x0 = gtb[4*g+0], y0 = gtb[4*g+1], x1 = gtb[4*g+2], y1 = gtb[4*g+3];
        sg0[tid] = make_float4(x0, y0, x1, y1);
        float gcx = (x0 + x1) * 0.5f, gcy = (y0 + y1) * 0.5f;
        float area = fmaxf(x1 - x0, 0.f) * fmaxf(y1 - y0, 0.f);
        sg1[tid] = make_float4(gcx, gcy, area, __int_as_float(gtl[g] * N));
    }
    __syncthreads();

    int n = blockIdx.x * blockDim.x + tid;
    if (n >= N) return;
    float4 pq = ((const float4*)priors)[n];
    float px = pq.x, py = pq.y;
    float a1 = px + CRAD * pq.z, a2 = px - CRAD * pq.z;
    float b1 = py + CRAD * pq.w, b2 = py - CRAD * pq.w;
    float4 dq = ((const float4*)dec)[n];
    float dx0 = dq.x, dy0 = dq.y, dx1 = dq.z, dy1 = dq.w;
    float aa = fmaxf(dx1 - dx0, 0.f) * fmaxf(dy1 - dy0, 0.f);
    float sL1 = g_sumL1[n];

    bool vacc = false;
    ull kmin = ~0ULL;
    int base = g0 * N + n;
    for (int gi = 0; gi < gcnt; gi++) {
        float4 q0 = sg0[gi];
        float4 q1 = sg1[gi];
        float m1 = fminf(fminf(px - q0.x, py - q0.y), fminf(q0.z - px, q0.w - py));
        float m2 = fminf(fminf(a1 - q1.x, b1 - q1.y), fminf(q1.x - a2, q1.y - b2));
        bool ing = m1 > 0.f, inc = m2 > 0.f;
        vacc = vacc || ing || inc;
        float w = fmaxf(fminf(dx1, q0.z) - fmaxf(dx0, q0.x), 0.f);
        float h = fmaxf(fminf(dy1, q0.w) - fmaxf(dy0, q0.y), 0.f);
        float inter = w * h;
        float uni = fmaxf(aa + q1.z - inter, EPSF);
        float iou = __fdividef(inter, uni);
        float cls = -g_D[__float_as_int(q1.w) + n] - sL1;
        float cost = cls - 3.0f * __logf(iou + EPSF);
        if (!(ing && inc)) cost += INF_F;
        G_IC[base] = make_float2(iou, cost);
        base += N;
        ull key = ((ull)fkey(cost) << 32) | (unsigned)(g0 + gi);
        kmin = umin64(kmin, key);
    }
    atomicMin(&g_amin[n], kmin);
    unsigned m = __ballot_sync(__activemask(), vacc);
    if ((tid & 31) == 0 && m) atomicOr(&g_valid[n >> 5], m);
}

// -------- kTopPart: grid (G, SPLIT). float-threshold sampling + compaction.
//          Last block per g merges + dynamic_k + atomics. (measured-best) ----
__global__ void __launch_bounds__(TPB) kTopPart(int N) {
    __shared__ ull   sbuf[2][CAP];
    __shared__ float ssamp[2][16];
    __shared__ float sT[2];
    __shared__ int   scnt[2];
    __shared__ ull   skeep[2][TK];
    __shared__ int   sfl, sdk;

    int g = blockIdx.x, s = blockIdx.y;
    int tid = threadIdx.x, lane = tid & 31, w = tid >> 5;
    int len = (((N + SPLIT - 1) / SPLIT) + 3) & ~3;
    int n0 = s * len;
    int n1 = min(N, n0 + len);
    const float2* col = G_IC + g * N;

    if (tid < 2) scnt[tid] = 0;

    // phase A: per-thread float top-2, vectorized full scan
    float i1 = -1.f, i2 = -1.f;
    float c1 = 3.0e38f, c2 = 3.0e38f;
    int nfull = n0 + (((n1 - n0) / 4) * 4);
    for (int n = n0 + tid * 4; n < nfull; n += TPB * 4) {
        float4 v0 = *reinterpret_cast<const float4*>(col + n);
        float4 v1 = *reinterpret_cast<const float4*>(col + n + 2);
        unsigned wv = g_valid[n >> 5] >> (n & 31);
        float io[4] = { (wv & 1u) ? v0.x : 0.f, (wv & 2u) ? v0.z : 0.f,
                        (wv & 4u) ? v1.x : 0.f, (wv & 8u) ? v1.z : 0.f };
        float co[4] = { (wv & 1u) ? v0.y : BIG_F, (wv & 2u) ? v0.w : BIG_F,
                        (wv & 4u) ? v1.y : BIG_F, (wv & 8u) ? v1.w : BIG_F };
        #pragma unroll
        for (int k = 0; k < 4; k++) {
            if (io[k] > i2) { if (io[k] > i1) { i2 = i1; i1 = io[k]; } else i2 = io[k]; }
            if (co[k] < c2) { if (co[k] < c1) { c2 = c1; c1 = co[k]; } else c2 = co[k]; }
        }
    }
    for (int n = nfull + tid; n < n1; n += TPB) {
        float2 p = col[n];
        bool vd = (g_valid[n >> 5] >> (n & 31)) & 1u;
        float io = vd ? p.x : 0.f;
        float co = vd ? p.y : BIG_F;
        if (io > i2) { if (io > i1) { i2 = i1; i1 = io; } else i2 = io; }
        if (co < c2) { if (co < c1) { c2 = c1; c1 = co; } else c2 = co; }
    }
    #pragma unroll
    for (int off = 16; off; off >>= 1) {
        float oi1 = __shfl_xor_sync(FULLM, i1, off);
        float oi2 = __shfl_xor_sync(FULLM, i2, off);
        float ni1 = fmaxf(i1, oi1);
        float ni2 = fmaxf(fminf(i1, oi1), fmaxf(i2, oi2));
        i1 = ni1; i2 = ni2;
        float oc1 = __shfl_xor_sync(FULLM, c1, off);
        float oc2 = __shfl_xor_sync(FULLM, c2, off);
        float nc1 = fminf(c1, oc1);
        float nc2 = fminf(fmaxf(c1, oc1), fminf(c2, oc2));
        c1 = nc1; c2 = nc2;
    }
    if (lane == 0) {
        ssamp[0][2 * w] = i1; ssamp[0][2 * w + 1] = i2;
        ssamp[1][2 * w] = c1; ssamp[1][2 * w + 1] = c2;
    }
    __syncthreads();

    // threshold: 10th best of 16 samples (ties via lane)
    if (w < 2) {
        float v = (lane < 16) ? ssamp[w][lane] : (w ? 3.0e38f : -1.f);
        int cnt = 0;
        #pragma unroll
        for (int j = 0; j < 16; j++) {
            float o = __shfl_sync(FULLM, v, j);
            bool better = (w == 0) ? (o > v) : (o < v);
            cnt += (better || (o == v && j < lane)) ? 1 : 0;
        }
        unsigned sel = __ballot_sync(FULLM, lane < 16 && cnt == 9);
        int l = __ffs(sel) - 1;
        float T = __shfl_sync(FULLM, v, l);
        if (lane == 0) sT[w] = T;
    }
    __syncthreads();
    float Ti = sT[0], Tc = sT[1];

    // phase B: compaction
    for (int n = n0 + tid * 4; n < nfull; n += TPB * 4) {
        float4 v0 = *reinterpret_cast<const float4*>(col + n);
        float4 v1 = *reinterpret_cast<const float4*>(col + n + 2);
        unsigned wv = g_valid[n >> 5] >> (n & 31);
        float io[4] = { (wv & 1u) ? v0.x : 0.f, (wv & 2u) ? v0.z : 0.f,
                        (wv & 4u) ? v1.x : 0.f, (wv & 8u) ? v1.z : 0.f };
        float co[4] = { (wv & 1u) ? v0.y : BIG_F, (wv & 2u) ? v0.w : BIG_F,
                        (wv & 4u) ? v1.y : BIG_F, (wv & 8u) ? v1.w : BIG_F };
        #pragma unroll
        for (int k = 0; k < 4; k++) {
            int ni = n + k;
            if (io[k] >= Ti) {
                ull key = ((ull)(unsigned)~fkey(io[k]) << 32) | (unsigned)ni;
                int p = atomicAdd(&scnt[0], 1); if (p < CAP) sbuf[0][p] = key;
            }
            if (co[k] <= Tc) {
                ull key = ((ull)fkey(co[k]) << 32) | (unsigned)ni;
                int p = atomicAdd(&scnt[1], 1); if (p < CAP) sbuf[1][p] = key;
            }
        }
    }
    for (int n = nfull + tid; n < n1; n += TPB) {
        float2 p = col[n];
        bool vd = (g_valid[n >> 5] >> (n & 31)) & 1u;
        float io = vd ? p.x : 0.f;
        float co = vd ? p.y : BIG_F;
        if (io >= Ti) {
            ull key = ((ull)(unsigned)~fkey(io) << 32) | (unsigned)n;
            int q = atomicAdd(&scnt[0], 1); if (q < CAP) sbuf[0][q] = key;
        }
        if (co <= Tc) {
            ull key = ((ull)fkey(co) << 32) | (unsigned)n;
            int q = atomicAdd(&scnt[1], 1); if (q < CAP) sbuf[1][q] = key;
        }
    }
    __syncthreads();

    // exact top-10 extraction from buffers
    if (w < 2) {
        int cnt = min(scnt[w], CAP);
        ull* buf = sbuf[w];
        for (int r = 0; r < TK; r++) {
            ull m = ~0ULL;
            for (int i = lane; i < cnt; i += 32) m = umin64(m, buf[i]);
            #pragma unroll
            for (int off = 16; off; off >>= 1)
                m = umin64(m, __shfl_xor_sync(FULLM, m, off));
            for (int i = lane; i < cnt; i += 32)
                if (buf[i] == m) buf[i] = ~0ULL;
            if (lane == 0) skeep[w][r] = m;
        }
    }
    __syncthreads();
    if (w == 0 && lane < TK) g_piou [(g * SPLIT + s) * TK + lane] = skeep[0][lane];
    if (w == 1 && lane < TK) g_pcost[(g * SPLIT + s) * TK + lane] = skeep[1][lane];
    __syncthreads();
    if (tid == 0) {
        __threadfence();
        int old = atomicAdd(&g_done[g], 1);
        sfl = (old == (int)gridDim.y - 1);
    }
    __syncthreads();
    if (!sfl) return;

    // last block for g: merge 80 keys per list
    if (w < 2) {
        const ull* src = (w == 0) ? &g_piou[g * TOTK] : &g_pcost[g * TOTK];
        ull k0 = (lane      < TOTK) ? __ldcg(&src[lane])      : ~0ULL;
        ull k1 = (lane + 32 < TOTK) ? __ldcg(&src[lane + 32]) : ~0ULL;
        ull k2 = (lane + 64 < TOTK) ? __ldcg(&src[lane + 64]) : ~0ULL;
        for (int r = 0; r < TK; r++) {
            ull m = umin64(k0, umin64(k1, k2));
            #pragma unroll
            for (int off = 16; off; off >>= 1)
                m = umin64(m, __shfl_xor_sync(FULLM, m, off));
            if (k0 == m) k0 = ~0ULL;
            else if (k1 == m) k1 = ~0ULL;
            else if (k2 == m) k2 = ~0ULL;
            if (lane == 0) skeep[w][r] = m;
        }
    }
    __syncthreads();
    if (tid == 0) {
        float ssum = 0.f;
        #pragma unroll
        for (int r = 0; r < TK; r++) {
            ull k = skeep[0][r];
            if (k != ~0ULL) ssum += unfkey(~(unsigned)(k >> 32));
        }
        int dk = (int)ssum;
        sdk = dk < 1 ? 1 : (dk > TK ? TK : dk);
    }
    __syncthreads();
    if (tid < sdk) {
        ull k = skeep[1][tid];
        if (k != ~0ULL) {
            int n = (int)(unsigned)k;
            atomicAdd(&g_cnt[n], 1);
            atomicMin(&g_mg[n], g);
        }
    }
}

// -------- finalize: no row scan; uses precomputed row argmin --------
__global__ void kFinal(float* __restrict__ out, int N, int G) {
    int n = blockIdx.x * blockDim.x + threadIdx.x;
    if (n >= N) return;
    int c = g_cnt[n];
    bool val = (g_valid[n >> 5] >> (n & 31)) & 1u;
    float gi = 0.f, lb = -1.f, io = -INF_F;
    if (c == 1) {
        int g = g_mg[n];
        gi = (float)g; lb = 1.f;
        io = val ? G_IC[g * N + n].x : 0.f;
    } else if (c > 1) {
        lb = 1.f;
        if (!val) { gi = 0.f; io = 0.f; }
        else {
            int bg = (int)(unsigned)g_amin[n];
            gi = (float)bg;
            io = G_IC[bg * N + n].x;
        }
    }
    out[n] = gi;
    out[N + n] = lb;
    out[2 * N + n] = io;
}

extern "C" void kernel_launch(void* const* d_in, const int* in_sizes, int n_in,
                              void* d_out, int out_size) {
    const float* ps  = (const float*)d_in[0];
    const float* pri = (const float*)d_in[1];
    const float* dec = (const float*)d_in[2];
    const float* gtb = (const float*)d_in[3];
    const int*   gtl = (const int*)d_in[4];
    int N = in_sizes[1] / 4;
    int G = in_sizes[3] / 4;
    int C = in_sizes[0] / N;
    if (N > NMAX || G > GMAX || C > CMAX) return;
    float* out = (float*)d_out;
    (void)out_size; (void)n_in;

    if (C == 80) {
        kAB<<<(N + 63) / 64, 256>>>(ps, pri, dec, gtb, gtl, N, G);
    } else {
        kSetup<<<(N + TPB - 1) / TPB, TPB>>>(N, G);
        kAgen<<<(N + TPB - 1) / TPB, TPB>>>(ps, N, C);
        dim3 gb((N + TPB - 1) / TPB, (G + GTILE - 1) / GTILE);
        kB<<<gb, TPB>>>(pri, dec, gtb, gtl, N, G);
    }
    dim3 gt(G, SPLIT);
    kTopPart<<<gt, TPB>>>(N);
    kFinal<<<(N + TPB - 1) / TPB, TPB>>>(out, N, G);
}

// round 15
// speedup vs baseline: 1.0241x; 1.0241x over previous
#include <cuda_runtime.h>
#include <stdint.h>

#define NMAX 33600
#define GMAX 128
#define CMAX 80
#define TPB 256
#define TK 10
#define GTILE 16
#define SPLIT 8
#define NW (TPB / 32)
#define CAP 768
#define TOTK (SPLIT * TK)               // 80 partial keys per gt per list
#define EPSF 1e-7f
#define INF_F 100000.0f
#define BIG_F 100000000.0f
#define CRAD 2.5f
#define NWORDS ((NMAX + 31) / 32)
#define FULLM 0xffffffffu

typedef unsigned long long ull;

// ---- scratch as __device__ globals (allocation-free rule) ----
__device__ float    g_D[(size_t)CMAX * NMAX];    // fallback path only
__device__ float    g_sumL1[NMAX];               // fallback path only
__device__ float4   g_ic4[(size_t)GMAX * NMAX / 2];   // {iou,cost} pairs, 16B-aligned
#define G_IC ((float2*)g_ic4)
__device__ unsigned g_valid[NWORDS];
__device__ int      g_cnt[NMAX];
__device__ int      g_mg[NMAX];
__device__ ull      g_amin[NMAX];                // row argmin: (fkey(cost)<<32)|g
__device__ int      g_done[GMAX];
__device__ ull      g_piou [GMAX * TOTK];
__device__ ull      g_pcost[GMAX * TOTK];

// monotone float->uint (ascending order preserved)
__device__ __forceinline__ unsigned fkey(float f) {
    unsigned u = __float_as_uint(f);
    return (u & 0x80000000u) ? ~u : (u | 0x80000000u);
}
__device__ __forceinline__ float unfkey(unsigned k) {
    unsigned u = (k & 0x80000000u) ? (k ^ 0x80000000u) : ~k;
    return __uint_as_float(u);
}

__device__ __forceinline__ ull umin64(ull a, ull b) { return a < b ? a : b; }

// ============ kAB: fully fused logits + pairwise (C==80 fast path) ==========
// Block = 256 threads, 128 anchors. Thread (a = tid&127, h = tid>>7) covers
// anchor a x GT-half h. Logit matrix lives in smem; g_D never touched.
// g_amin and g_valid become plain stores (full row visible in-block).
__global__ void __launch_bounds__(256) kAB(
    const float* __restrict__ ps, const float* __restrict__ priors,
    const float* __restrict__ dec, const float* __restrict__ gtb,
    const int* __restrict__ gtl, int N, int G)
{
    __shared__ float    sD[80 * 129];     // [c][a], stride 129 (conflict-free)
    __shared__ float    sPart[2 * 128];   // per-half partial sumL1
    __shared__ float4   sg0[GMAX];
    __shared__ float4   sg1[GMAX];
    __shared__ ull      skm[256];
    __shared__ unsigned sb[8];

    int tid = threadIdx.x;
    int n0 = blockIdx.x * 128;
    int rows = min(128, N - n0);

    // fused setup
    if (tid < rows) { g_cnt[n0 + tid] = 0; g_mg[n0 + tid] = 0x7fffffff; }
    if (blockIdx.x == 0 && tid < GMAX) g_done[tid] = 0;

    // gt descriptors (label pre-scaled by smem row stride 129)
    if (tid < G) {
        int g = tid;
        float x0 = gtb[4*g+0], y0 = gtb[4*g+1], x1 = gtb[4*g+2], y1 = gtb[4*g+3];
        sg0[g] = make_float4(x0, y0, x1, y1);
        float gcx = (x0 + x1) * 0.5f, gcy = (y0 + y1) * 0.5f;
        float area = fmaxf(x1 - x0, 0.f) * fmaxf(y1 - y0, 0.f);
        sg1[g] = make_float4(gcx, gcy, area, __int_as_float(gtl[g] * 129));
    }

    // stage ps coalesced into sD (as raw p)
    for (int i = tid; i < rows * 80; i += 256) {
        int a = i / 80, c = i - a * 80;
        sD[c * 129 + a] = ps[n0 * 80 + i];
    }
    __syncthreads();

    int a = tid & 127, h = tid >> 7;

    // phase 1: logits in place + grouped-product partial sumL1 (8 groups of 5)
    if (a < rows) {
        float gl = 0.f;
        #pragma unroll
        for (int k2 = 0; k2 < 8; k2++) {
            float prod = 1.f;
            #pragma unroll
            for (int m = 0; m < 5; m++) {
                int c = h * 40 + k2 * 5 + m;
                float p = sD[c * 129 + a];
                float q = 1.f - p;
                prod *= q;
                sD[c * 129 + a] = __logf(__fdividef(p, q));
            }
            gl += __logf(prod);
        }
        sPart[h * 128 + a] = gl;
    }
    __syncthreads();

    // phase 2: pairwise over this thread's GT half
    int n = n0 + a;
    bool vacc = false;
    ull kmin = ~0ULL;
    int half = (G + 1) >> 1;
    int gs = h * half;
    int ge = min(G, gs + half);
    if (a < rows) {
        float4 pq = ((const float4*)priors)[n];
        float px = pq.x, py = pq.y;
        float a1 = px + CRAD * pq.z, a2 = px - CRAD * pq.z;
        float b1 = py + CRAD * pq.w, b2 = py - CRAD * pq.w;
        float4 dq = ((const float4*)dec)[n];
        float dx0 = dq.x, dy0 = dq.y, dx1 = dq.z, dy1 = dq.w;
        float aa = fmaxf(dx1 - dx0, 0.f) * fmaxf(dy1 - dy0, 0.f);
        float sL1 = sPart[a] + sPart[128 + a];
        int base = gs * N + n;
        #pragma unroll 4
        for (int g = gs; g < ge; g++) {
            float4 q0 = sg0[g];
            float4 q1 = sg1[g];
            float m1 = fminf(fminf(px - q0.x, py - q0.y), fminf(q0.z - px, q0.w - py));
            float m2 = fminf(fminf(a1 - q1.x, b1 - q1.y), fminf(q1.x - a2, q1.y - b2));
            bool ing = m1 > 0.f, inc = m2 > 0.f;
            vacc = vacc || ing || inc;
            float w = fmaxf(fminf(dx1, q0.z) - fmaxf(dx0, q0.x), 0.f);
            float hh = fmaxf(fminf(dy1, q0.w) - fmaxf(dy0, q0.y), 0.f);
            float inter = w * hh;
            float uni = fmaxf(aa + q1.z - inter, EPSF);
            float iou = __fdividef(inter, uni);
            float cls = -sD[__float_as_int(q1.w) + a] - sL1;
            float cost = cls - 3.0f * __logf(iou + EPSF);
            if (!(ing && inc)) cost += INF_F;
            G_IC[base] = make_float2(iou, cost);
            base += N;
            kmin = umin64(kmin, ((ull)fkey(cost) << 32) | (unsigned)g);
        }
    }
    skm[tid] = kmin;
    unsigned bal = __ballot_sync(FULLM, vacc);
    if ((tid & 31) == 0) sb[tid >> 5] = bal;
    __syncthreads();
    if (tid < 128 && tid < rows)
        g_amin[n0 + tid] = umin64(skm[tid], skm[tid + 128]);
    if (tid < 4 && tid * 32 < rows)
        g_valid[(n0 >> 5) + tid] = sb[tid] | sb[tid + 4];
}

// -------- generic fallbacks (C != 80; not used for this problem's shapes) ----
__global__ void kSetup(int N, int G) {
    int i = blockIdx.x * blockDim.x + threadIdx.x;
    if (i < N) { g_cnt[i] = 0; g_mg[i] = 0x7fffffff; g_amin[i] = ~0ULL; }
    if (i < NWORDS) g_valid[i] = 0u;
    if (i < GMAX) g_done[i] = 0;
}
__global__ void kAgen(const float* __restrict__ ps, int N, int C) {
    int n = blockIdx.x * blockDim.x + threadIdx.x;
    if (n >= N) return;
    float ssum = 0.f;
    for (int c = 0; c < C; c++) {
        float p = ps[(size_t)n * C + c];
        float L  = fmaxf(__logf(p), -100.f);
        float L1 = fmaxf(__logf(1.f - p), -100.f);
        g_D[c * N + n] = L - L1;
        ssum += L1;
    }
    g_sumL1[n] = ssum;
}
__global__ void __launch_bounds__(TPB) kB(
    const float* __restrict__ priors, const float* __restrict__ dec,
    const float* __restrict__ gtb, const int* __restrict__ gtl,
    int N, int G)
{
    __shared__ float4 sg0[GTILE];
    __shared__ float4 sg1[GTILE];
    int tid = threadIdx.x;
    int g0 = blockIdx.y * GTILE;
    int gcnt = min(GTILE, G - g0);
    if (tid < gcnt) {
        int g = g0 + tid;
        float x0 = gtb[4*g+0], y0 = gtb[4*g+1], x1 = gtb[4*g+2], y1 = gtb[4*g+3];
        sg0[tid] = make_float4(x0, y0, x1, y1);
        float gcx = (x0 + x1) * 0.5f, gcy = (y0 + y1) * 0.5f;
        float area = fmaxf(x1 - x0, 0.f) * fmaxf(y1 - y0, 0.f);
        sg1[tid] = make_float4(gcx, gcy, area, __int_as_float(gtl[g] * N));
    }
    __syncthreads();

    int n = blockIdx.x * blockDim.x + tid;
    if (n >= N) return;
    float4 pq = ((const float4*)priors)[n];
    float px = pq.x, py = pq.y;
    float a1 = px + CRAD * pq.z, a2 = px - CRAD * pq.z;
    float b1 = py + CRAD * pq.w, b2 = py - CRAD * pq.w;
    float4 dq = ((const float4*)dec)[n];
    float dx0 = dq.x, dy0 = dq.y, dx1 = dq.z, dy1 = dq.w;
    float aa = fmaxf(dx1 - dx0, 0.f) * fmaxf(dy1 - dy0, 0.f);
    float sL1 = g_sumL1[n];

    bool vacc = false;
    ull kmin = ~0ULL;
    int base = g0 * N + n;
    for (int gi = 0; gi < gcnt; gi++) {
        float4 q0 = sg0[gi];
        float4 q1 = sg1[gi];
        float m1 = fminf(fminf(px - q0.x, py - q0.y), fminf(q0.z - px, q0.w - py));
        float m2 = fminf(fminf(a1 - q1.x, b1 - q1.y), fminf(q1.x - a2, q1.y - b2));
        bool ing = m1 > 0.f, inc = m2 > 0.f;
        vacc = vacc || ing || inc;
        float w = fmaxf(fminf(dx1, q0.z) - fmaxf(dx0, q0.x), 0.f);
        float h = fmaxf(fminf(dy1, q0.w) - fmaxf(dy0, q0.y), 0.f);
        float inter = w * h;
        float uni = fmaxf(aa + q1.z - inter, EPSF);
        float iou = __fdividef(inter, uni);
        float cls = -g_D[__float_as_int(q1.w) + n] - sL1;
        float cost = cls - 3.0f * __logf(iou + EPSF);
        if (!(ing && inc)) cost += INF_F;
        G_IC[base] = make_float2(iou, cost);
        base += N;
        ull key = ((ull)fkey(cost) << 32) | (unsigned)(g0 + gi);
        kmin = umin64(kmin, key);
    }
    atomicMin(&g_amin[n], kmin);
    unsigned m = __ballot_sync(__activemask(), vacc);
    if ((tid & 31) == 0 && m) atomicOr(&g_valid[n >> 5], m);
}

// -------- kTopPart: grid (G, SPLIT). float-threshold sampling + compaction.
//          Last block per g merges + dynamic_k + atomics. (measured-best) ----
__global__ void __launch_bounds__(TPB) kTopPart(int N) {
    __shared__ ull   sbuf[2][CAP];
    __shared__ float ssamp[2][16];
    __shared__ float sT[2];
    __shared__ int   scnt[2];
    __shared__ ull   skeep[2][TK];
    __shared__ int   sfl, sdk;

    int g = blockIdx.x, s = blockIdx.y;
    int tid = threadIdx.x, lane = tid & 31, w = tid >> 5;
    int len = (((N + SPLIT - 1) / SPLIT) + 3) & ~3;
    int n0 = s * len;
    int n1 = min(N, n0 + len);
    const float2* col = G_IC + g * N;

    if (tid < 2) scnt[tid] = 0;

    // phase A: per-thread float top-2, vectorized full scan
    float i1 = -1.f, i2 = -1.f;
    float c1 = 3.0e38f, c2 = 3.0e38f;
    int nfull = n0 + (((n1 - n0) / 4) * 4);
    for (int n = n0 + tid * 4; n < nfull; n += TPB * 4) {
        float4 v0 = *reinterpret_cast<const float4*>(col + n);
        float4 v1 = *reinterpret_cast<const float4*>(col + n + 2);
        unsigned wv = g_valid[n >> 5] >> (n & 31);
        float io[4] = { (wv & 1u) ? v0.x : 0.f, (wv & 2u) ? v0.z : 0.f,
                        (wv & 4u) ? v1.x : 0.f, (wv & 8u) ? v1.z : 0.f };
        float co[4] = { (wv & 1u) ? v0.y : BIG_F, (wv & 2u) ? v0.w : BIG_F,
                        (wv & 4u) ? v1.y : BIG_F, (wv & 8u) ? v1.w : BIG_F };
        #pragma unroll
        for (int k = 0; k < 4; k++) {
            if (io[k] > i2) { if (io[k] > i1) { i2 = i1; i1 = io[k]; } else i2 = io[k]; }
            if (co[k] < c2) { if (co[k] < c1) { c2 = c1; c1 = co[k]; } else c2 = co[k]; }
        }
    }
    for (int n = nfull + tid; n < n1; n += TPB) {
        float2 p = col[n];
        bool vd = (g_valid[n >> 5] >> (n & 31)) & 1u;
        float io = vd ? p.x : 0.f;
        float co = vd ? p.y : BIG_F;
        if (io > i2) { if (io > i1) { i2 = i1; i1 = io; } else i2 = io; }
        if (co < c2) { if (co < c1) { c2 = c1; c1 = co; } else c2 = co; }
    }
    #pragma unroll
    for (int off = 16; off; off >>= 1) {
        float oi1 = __shfl_xor_sync(FULLM, i1, off);
        float oi2 = __shfl_xor_sync(FULLM, i2, off);
        float ni1 = fmaxf(i1, oi1);
        float ni2 = fmaxf(fminf(i1, oi1), fmaxf(i2, oi2));
        i1 = ni1; i2 = ni2;
        float oc1 = __shfl_xor_sync(FULLM, c1, off);
        float oc2 = __shfl_xor_sync(FULLM, c2, off);
        float nc1 = fminf(c1, oc1);
        float nc2 = fminf(fmaxf(c1, oc1), fminf(c2, oc2));
        c1 = nc1; c2 = nc2;
    }
    if (lane == 0) {
        ssamp[0][2 * w] = i1; ssamp[0][2 * w + 1] = i2;
        ssamp[1][2 * w] = c1; ssamp[1][2 * w + 1] = c2;
    }
    __syncthreads();

    // threshold: 10th best of 16 samples (ties via lane)
    if (w < 2) {
        float v = (lane < 16) ? ssamp[w][lane] : (w ? 3.0e38f : -1.f);
        int cnt = 0;
        #pragma unroll
        for (int j = 0; j < 16; j++) {
            float o = __shfl_sync(FULLM, v, j);
            bool better = (w == 0) ? (o > v) : (o < v);
            cnt += (better || (o == v && j < lane)) ? 1 : 0;
        }
        unsigned sel = __ballot_sync(FULLM, lane < 16 && cnt == 9);
        int l = __ffs(sel) - 1;
        float T = __shfl_sync(FULLM, v, l);
        if (lane == 0) sT[w] = T;
    }
    __syncthreads();
    float Ti = sT[0], Tc = sT[1];

    // phase B: compaction
    for (int n = n0 + tid * 4; n < nfull; n += TPB * 4) {
        float4 v0 = *reinterpret_cast<const float4*>(col + n);
        float4 v1 = *reinterpret_cast<const float4*>(col + n + 2);
        unsigned wv = g_valid[n >> 5] >> (n & 31);
        float io[4] = { (wv & 1u) ? v0.x : 0.f, (wv & 2u) ? v0.z : 0.f,
                        (wv & 4u) ? v1.x : 0.f, (wv & 8u) ? v1.z : 0.f };
        float co[4] = { (wv & 1u) ? v0.y : BIG_F, (wv & 2u) ? v0.w : BIG_F,
                        (wv & 4u) ? v1.y : BIG_F, (wv & 8u) ? v1.w : BIG_F };
        #pragma unroll
        for (int k = 0; k < 4; k++) {
            int ni = n + k;
            if (io[k] >= Ti) {
                ull key = ((ull)(unsigned)~fkey(io[k]) << 32) | (unsigned)ni;
                int p = atomicAdd(&scnt[0], 1); if (p < CAP) sbuf[0][p] = key;
            }
            if (co[k] <= Tc) {
                ull key = ((ull)fkey(co[k]) << 32) | (unsigned)ni;
                int p = atomicAdd(&scnt[1], 1); if (p < CAP) sbuf[1][p] = key;
            }
        }
    }
    for (int n = nfull + tid; n < n1; n += TPB) {
        float2 p = col[n];
        bool vd = (g_valid[n >> 5] >> (n & 31)) & 1u;
        float io = vd ? p.x : 0.f;
        float co = vd ? p.y : BIG_F;
        if (io >= Ti) {
            ull key = ((ull)(unsigned)~fkey(io) << 32) | (unsigned)n;
            int q = atomicAdd(&scnt[0], 1); if (q < CAP) sbuf[0][q] = key;
        }
        if (co <= Tc) {
            ull key = ((ull)fkey(co) << 32) | (unsigned)n;
            int q = atomicAdd(&scnt[1], 1); if (q < CAP) sbuf[1][q] = key;
        }
    }
    __syncthreads();

    // exact top-10 extraction from buffers
    if (w < 2) {
        int cnt = min(scnt[w], CAP);
        ull* buf = sbuf[w];
        for (int r = 0; r < TK; r++) {
            ull m = ~0ULL;
            for (int i = lane; i < cnt; i += 32) m = umin64(m, buf[i]);
            #pragma unroll
            for (int off = 16; off; off >>= 1)
                m = umin64(m, __shfl_xor_sync(FULLM, m, off));
            for (int i = lane; i < cnt; i += 32)
                if (buf[i] == m) buf[i] = ~0ULL;
            if (lane == 0) skeep[w][r] = m;
        }
    }
    __syncthreads();
    if (w == 0 && lane < TK) g_piou [(g * SPLIT + s) * TK + lane] = skeep[0][lane];
    if (w == 1 && lane < TK) g_pcost[(g * SPLIT + s) * TK + lane] = skeep[1][lane];
    __syncthreads();
    if (tid == 0) {
        __threadfence();
        int old = atomicAdd(&g_done[g], 1);
        sfl = (old == (int)gridDim.y - 1);
    }
    __syncthreads();
    if (!sfl) return;

    // last block for g: merge 80 keys per list
    if (w < 2) {
        const ull* src = (w == 0) ? &g_piou[g * TOTK] : &g_pcost[g * TOTK];
        ull k0 = (lane      < TOTK) ? __ldcg(&src[lane])      : ~0ULL;
        ull k1 = (lane + 32 < TOTK) ? __ldcg(&src[lane + 32]) : ~0ULL;
        ull k2 = (lane + 64 < TOTK) ? __ldcg(&src[lane + 64]) : ~0ULL;
        for (int r = 0; r < TK; r++) {
            ull m = umin64(k0, umin64(k1, k2));
            #pragma unroll
            for (int off = 16; off; off >>= 1)
                m = umin64(m, __shfl_xor_sync(FULLM, m, off));
            if (k0 == m) k0 = ~0ULL;
            else if (k1 == m) k1 = ~0ULL;
            else if (k2 == m) k2 = ~0ULL;
            if (lane == 0) skeep[w][r] = m;
        }
    }
    __syncthreads();
    if (tid == 0) {
        float ssum = 0.f;
        #pragma unroll
        for (int r = 0; r < TK; r++) {
            ull k = skeep[0][r];
            if (k != ~0ULL) ssum += unfkey(~(unsigned)(k >> 32));
        }
        int dk = (int)ssum;
        sdk = dk < 1 ? 1 : (dk > TK ? TK : dk);
    }
    __syncthreads();
    if (tid < sdk) {
        ull k = skeep[1][tid];
        if (k != ~0ULL) {
            int n = (int)(unsigned)k;
            atomicAdd(&g_cnt[n], 1);
            atomicMin(&g_mg[n], g);
        }
    }
}

// -------- finalize: no row scan; uses precomputed row argmin --------
__global__ void kFinal(float* __restrict__ out, int N, int G) {
    int n = blockIdx.x * blockDim.x + threadIdx.x;
    if (n >= N) return;
    int c = g_cnt[n];
    bool val = (g_valid[n >> 5] >> (n & 31)) & 1u;
    float gi = 0.f, lb = -1.f, io = -INF_F;
    if (c == 1) {
        int g = g_mg[n];
        gi = (float)g; lb = 1.f;
        io = val ? G_IC[g * N + n].x : 0.f;
    } else if (c > 1) {
        lb = 1.f;
        if (!val) { gi = 0.f; io = 0.f; }
        else {
            int bg = (int)(unsigned)g_amin[n];
            gi = (float)bg;
            io = G_IC[bg * N + n].x;
        }
    }
    out[n] = gi;
    out[N + n] = lb;
    out[2 * N + n] = io;
}

extern "C" void kernel_launch(void* const* d_in, const int* in_sizes, int n_in,
                              void* d_out, int out_size) {
    const float* ps  = (const float*)d_in[0];
    const float* pri = (const float*)d_in[1];
    const float* dec = (const float*)d_in[2];
    const float* gtb = (const float*)d_in[3];
    const int*   gtl = (const int*)d_in[4];
    int N = in_sizes[1] / 4;
    int G = in_sizes[3] / 4;
    int C = in_sizes[0] / N;
    if (N > NMAX || G > GMAX || C > CMAX) return;
    float* out = (float*)d_out;
    (void)out_size; (void)n_in;

    if (C == 80) {
        kAB<<<(N + 127) / 128, 256>>>(ps, pri, dec, gtb, gtl, N, G);
    } else {
        kSetup<<<(N + TPB - 1) / TPB, TPB>>>(N, G);
        kAgen<<<(N + TPB - 1) / TPB, TPB>>>(ps, N, C);
        dim3 gb((N + TPB - 1) / TPB, (G + GTILE - 1) / GTILE);
        kB<<<gb, TPB>>>(pri, dec, gtb, gtl, N, G);
    }
    dim3 gt(G, SPLIT);
    kTopPart<<<gt, TPB>>>(N);
    kFinal<<<(N + TPB - 1) / TPB, TPB>>>(out, N, G);
}

// round 16
// speedup vs baseline: 1.0548x; 1.0300x over previous
#include <cuda_runtime.h>
#include <stdint.h>

#define NMAX 33600
#define GMAX 128
#define CMAX 80
#define TPB 256
#define TK 10
#define GTILE 16
#define SPLIT 8
#define NW (TPB / 32)
#define CAP 768
#define TOTK (SPLIT * TK)               // 80 partial keys per gt per list
#define EPSF 1e-7f
#define INF_F 100000.0f
#define BIG_F 100000000.0f
#define CRAD 2.5f
#define NWORDS ((NMAX + 31) / 32)
#define FULLM 0xffffffffu

typedef unsigned long long ull;

// ---- scratch as __device__ globals (allocation-free rule) ----
__device__ float    g_D[(size_t)CMAX * NMAX];    // fallback path only
__device__ float    g_sumL1[NMAX];               // fallback path only
__device__ float4   g_ic4[(size_t)GMAX * NMAX / 2];   // {iou,cost} pairs, 16B-aligned
#define G_IC ((float2*)g_ic4)
__device__ unsigned g_valid[NWORDS];
__device__ int      g_cnt[NMAX];
__device__ int      g_mg[NMAX];
__device__ ull      g_amin[NMAX];                // row argmin: (fkey(cost)<<32)|g
__device__ int      g_done[GMAX];
__device__ ull      g_piou [GMAX * TOTK];
__device__ ull      g_pcost[GMAX * TOTK];

// monotone float->uint (ascending order preserved)
__device__ __forceinline__ unsigned fkey(float f) {
    unsigned u = __float_as_uint(f);
    return (u & 0x80000000u) ? ~u : (u | 0x80000000u);
}
__device__ __forceinline__ float unfkey(unsigned k) {
    unsigned u = (k & 0x80000000u) ? (k ^ 0x80000000u) : ~k;
    return __uint_as_float(u);
}

__device__ __forceinline__ ull umin64(ull a, ull b) { return a < b ? a : b; }

// ============ kAB: fully fused logits + pairwise (C==80 fast path) ==========
// Block = 256 threads, 128 anchors. Thread (a = tid&127, h = tid>>7) covers
// anchor a x GT-half h. Logit matrix lives in smem; g_D never touched.
// g_amin and g_valid are plain stores (full row visible in-block).
// Per-pair argmin uses strict float compare (g ascending => first-min);
// 64-bit key built once per thread at the end.
__global__ void __launch_bounds__(256) kAB(
    const float* __restrict__ ps, const float* __restrict__ priors,
    const float* __restrict__ dec, const float* __restrict__ gtb,
    const int* __restrict__ gtl, int N, int G)
{
    __shared__ float    sD[80 * 129];     // [c][a], stride 129 (conflict-free)
    __shared__ float    sPart[2 * 128];   // per-half partial sumL1
    __shared__ float4   sg0[GMAX];
    __shared__ float4   sg1[GMAX];
    __shared__ ull      skm[256];
    __shared__ unsigned sb[8];

    int tid = threadIdx.x;
    int n0 = blockIdx.x * 128;
    int rows = min(128, N - n0);

    // fused setup
    if (tid < rows) { g_cnt[n0 + tid] = 0; g_mg[n0 + tid] = 0x7fffffff; }
    if (blockIdx.x == 0 && tid < GMAX) g_done[tid] = 0;

    // gt descriptors (label pre-scaled by smem row stride 129)
    if (tid < G) {
        int g = tid;
        float x0 = gtb[4*g+0], y0 = gtb[4*g+1], x1 = gtb[4*g+2], y1 = gtb[4*g+3];
        sg0[g] = make_float4(x0, y0, x1, y1);
        float gcx = (x0 + x1) * 0.5f, gcy = (y0 + y1) * 0.5f;
        float area = fmaxf(x1 - x0, 0.f) * fmaxf(y1 - y0, 0.f);
        sg1[g] = make_float4(gcx, gcy, area, __int_as_float(gtl[g] * 129));
    }

    // stage ps coalesced into sD (as raw p)
    for (int i = tid; i < rows * 80; i += 256) {
        int a = i / 80, c = i - a * 80;
        sD[c * 129 + a] = ps[n0 * 80 + i];
    }
    __syncthreads();

    int a = tid & 127, h = tid >> 7;

    // phase 1: logits in place + grouped-product partial sumL1 (8 groups of 5)
    if (a < rows) {
        float gl = 0.f;
        #pragma unroll
        for (int k2 = 0; k2 < 8; k2++) {
            float prod = 1.f;
            #pragma unroll
            for (int m = 0; m < 5; m++) {
                int c = h * 40 + k2 * 5 + m;
                float p = sD[c * 129 + a];
                float q = 1.f - p;
                prod *= q;
                sD[c * 129 + a] = __logf(__fdividef(p, q));
            }
            gl += __logf(prod);
        }
        sPart[h * 128 + a] = gl;
    }
    __syncthreads();

    // phase 2: pairwise over this thread's GT half
    int n = n0 + a;
    bool vacc = false;
    float bestc = 3.4e38f;
    int   bestg = 0;
    int half = (G + 1) >> 1;
    int gs = h * half;
    int ge = min(G, gs + half);
    if (a < rows) {
        float4 pq = ((const float4*)priors)[n];
        float px = pq.x, py = pq.y;
        float a1 = px + CRAD * pq.z, a2 = px - CRAD * pq.z;
        float b1 = py + CRAD * pq.w, b2 = py - CRAD * pq.w;
        float4 dq = ((const float4*)dec)[n];
        float dx0 = dq.x, dy0 = dq.y, dx1 = dq.z, dy1 = dq.w;
        float aa = fmaxf(dx1 - dx0, 0.f) * fmaxf(dy1 - dy0, 0.f);
        float sL1 = sPart[a] + sPart[128 + a];
        int base = gs * N + n;
        #pragma unroll 4
        for (int g = gs; g < ge; g++) {
            float4 q0 = sg0[g];
            float4 q1 = sg1[g];
            float m1 = fminf(fminf(px - q0.x, py - q0.y), fminf(q0.z - px, q0.w - py));
            float m2 = fminf(fminf(a1 - q1.x, b1 - q1.y), fminf(q1.x - a2, q1.y - b2));
            bool ing = m1 > 0.f, inc = m2 > 0.f;
            vacc = vacc || ing || inc;
            float w = fmaxf(fminf(dx1, q0.z) - fmaxf(dx0, q0.x), 0.f);
            float hh = fmaxf(fminf(dy1, q0.w) - fmaxf(dy0, q0.y), 0.f);
            float inter = w * hh;
            float uni = fmaxf(aa + q1.z - inter, EPSF);
            float iou = __fdividef(inter, uni);
            float cls = -sD[__float_as_int(q1.w) + a] - sL1;
            float cost = cls - 3.0f * __logf(iou + EPSF);
            if (!(ing && inc)) cost += INF_F;
            G_IC[base] = make_float2(iou, cost);
            base += N;
            if (cost < bestc) { bestc = cost; bestg = g; }   // g ascending => first-min
        }
    }
    skm[tid] = (a < rows) ? (((ull)fkey(bestc) << 32) | (unsigned)bestg) : ~0ULL;
    unsigned bal = __ballot_sync(FULLM, vacc);
    if ((tid & 31) == 0) sb[tid >> 5] = bal;
    __syncthreads();
    if (tid < 128 && tid < rows)
        g_amin[n0 + tid] = umin64(skm[tid], skm[tid + 128]);
    if (tid < 4 && tid * 32 < rows)
        g_valid[(n0 >> 5) + tid] = sb[tid] | sb[tid + 4];
}

// -------- generic fallbacks (C != 80; not used for this problem's shapes) ----
__global__ void kSetup(int N, int G) {
    int i = blockIdx.x * blockDim.x + threadIdx.x;
    if (i < N) { g_cnt[i] = 0; g_mg[i] = 0x7fffffff; g_amin[i] = ~0ULL; }
    if (i < NWORDS) g_valid[i] = 0u;
    if (i < GMAX) g_done[i] = 0;
}
__global__ void kAgen(const float* __restrict__ ps, int N, int C) {
    int n = blockIdx.x * blockDim.x + threadIdx.x;
    if (n >= N) return;
    float ssum = 0.f;
    for (int c = 0; c < C; c++) {
        float p = ps[(size_t)n * C + c];
        float L  = fmaxf(__logf(p), -100.f);
        float L1 = fmaxf(__logf(1.f - p), -100.f);
        g_D[c * N + n] = L - L1;
        ssum += L1;
    }
    g_sumL1[n] = ssum;
}
__global__ void __launch_bounds__(TPB) kB(
    const float* __restrict__ priors, const float* __restrict__ dec,
    const float* __restrict__ gtb, const int* __restrict__ gtl,
    int N, int G)
{
    __shared__ float4 sg0[GTILE];
    __shared__ float4 sg1[GTILE];
    int tid = threadIdx.x;
    int g0 = blockIdx.y * GTILE;
    int gcnt = min(GTILE, G - g0);
    if (tid < gcnt) {
        int g = g0 + tid;
        float x0 = gtb[4*g+0], y0 = gtb[4*g+1], x1 = gtb[4*g+2], y1 = gtb[4*g+3];
        sg0[tid] = make_float4(x0, y0, x1, y1);
        float gcx = (x0 + x1) * 0.5f, gcy = (y0 + y1) * 0.5f;
        float area = fmaxf(x1 - x0, 0.f) * fmaxf(y1 - y0, 0.f);
        sg1[tid] = make_float4(gcx, gcy, area, __int_as_float(gtl[g] * N));
    }
    __syncthreads();

    int n = blockIdx.x * blockDim.x + tid;
    if (n >= N) return;
    float4 pq = ((const float4*)priors)[n];
    float px = pq.x, py = pq.y;
    float a1 = px + CRAD * pq.z, a2 = px - CRAD * pq.z;
    float b1 = py + CRAD * pq.w, b2 = py - CRAD * pq.w;
    float4 dq = ((const float4*)dec)[n];
    float dx0 = dq.x, dy0 = dq.y, dx1 = dq.z, dy1 = dq.w;
    float aa = fmaxf(dx1 - dx0, 0.f) * fmaxf(dy1 - dy0, 0.f);
    float sL1 = g_sumL1[n];

    bool vacc = false;
    ull kmin = ~0ULL;
    int base = g0 * N + n;
    for (int gi = 0; gi < gcnt; gi++) {
        float4 q0 = sg0[gi];
        float4 q1 = sg1[gi];
        float m1 = fminf(fminf(px - q0.x, py - q0.y), fminf(q0.z - px, q0.w - py));
        float m2 = fminf(fminf(a1 - q1.x, b1 - q1.y), fminf(q1.x - a2, q1.y - b2));
        bool ing = m1 > 0.f, inc = m2 > 0.f;
        vacc = vacc || ing || inc;
        float w = fmaxf(fminf(dx1, q0.z) - fmaxf(dx0, q0.x), 0.f);
        float h = fmaxf(fminf(dy1, q0.w) - fmaxf(dy0, q0.y), 0.f);
        float inter = w * h;
        float uni = fmaxf(aa + q1.z - inter, EPSF);
        float iou = __fdividef(inter, uni);
        float cls = -g_D[__float_as_int(q1.w) + n] - sL1;
        float cost = cls - 3.0f * __logf(iou + EPSF);
        if (!(ing && inc)) cost += INF_F;
        G_IC[base] = make_float2(iou, cost);
        base += N;
        ull key = ((ull)fkey(cost) << 32) | (unsigned)(g0 + gi);
        kmin = umin64(kmin, key);
    }
    atomicMin(&g_amin[n], kmin);
    unsigned m = __ballot_sync(__activemask(), vacc);
    if ((tid & 31) == 0 && m) atomicOr(&g_valid[n >> 5], m);
}

// -------- kTopPart: grid (G, SPLIT). float-threshold sampling + compaction.
//          Last block per g merges + dynamic_k + atomics. (measured-best) ----
__global__ void __launch_bounds__(TPB) kTopPart(int N) {
    __shared__ ull   sbuf[2][CAP];
    __shared__ float ssamp[2][16];
    __shared__ float sT[2];
    __shared__ int   scnt[2];
    __shared__ ull   skeep[2][TK];
    __shared__ int   sfl, sdk;

    int g = blockIdx.x, s = blockIdx.y;
    int tid = threadIdx.x, lane = tid & 31, w = tid >> 5;
    int len = (((N + SPLIT - 1) / SPLIT) + 3) & ~3;
    int n0 = s * len;
    int n1 = min(N, n0 + len);
    const float2* col = G_IC + g * N;

    if (tid < 2) scnt[tid] = 0;

    // phase A: per-thread float top-2, vectorized full scan
    float i1 = -1.f, i2 = -1.f;
    float c1 = 3.0e38f, c2 = 3.0e38f;
    int nfull = n0 + (((n1 - n0) / 4) * 4);
    for (int n = n0 + tid * 4; n < nfull; n += TPB * 4) {
        float4 v0 = *reinterpret_cast<const float4*>(col + n);
        float4 v1 = *reinterpret_cast<const float4*>(col + n + 2);
        unsigned wv = g_valid[n >> 5] >> (n & 31);
        float io[4] = { (wv & 1u) ? v0.x : 0.f, (wv & 2u) ? v0.z : 0.f,
                        (wv & 4u) ? v1.x : 0.f, (wv & 8u) ? v1.z : 0.f };
        float co[4] = { (wv & 1u) ? v0.y : BIG_F, (wv & 2u) ? v0.w : BIG_F,
                        (wv & 4u) ? v1.y : BIG_F, (wv & 8u) ? v1.w : BIG_F };
        #pragma unroll
        for (int k = 0; k < 4; k++) {
            if (io[k] > i2) { if (io[k] > i1) { i2 = i1; i1 = io[k]; } else i2 = io[k]; }
            if (co[k] < c2) { if (co[k] < c1) { c2 = c1; c1 = co[k]; } else c2 = co[k]; }
        }
    }
    for (int n = nfull + tid; n < n1; n += TPB) {
        float2 p = col[n];
        bool vd = (g_valid[n >> 5] >> (n & 31)) & 1u;
        float io = vd ? p.x : 0.f;
        float co = vd ? p.y : BIG_F;
        if (io > i2) { if (io > i1) { i2 = i1; i1 = io; } else i2 = io; }
        if (co < c2) { if (co < c1) { c2 = c1; c1 = co; } else c2 = co; }
    }
    #pragma unroll
    for (int off = 16; off; off >>= 1) {
        float oi1 = __shfl_xor_sync(FULLM, i1, off);
        float oi2 = __shfl_xor_sync(FULLM, i2, off);
        float ni1 = fmaxf(i1, oi1);
        float ni2 = fmaxf(fminf(i1, oi1), fmaxf(i2, oi2));
        i1 = ni1; i2 = ni2;
        float oc1 = __shfl_xor_sync(FULLM, c1, off);
        float oc2 = __shfl_xor_sync(FULLM, c2, off);
        float nc1 = fminf(c1, oc1);
        float nc2 = fminf(fmaxf(c1, oc1), fminf(c2, oc2));
        c1 = nc1; c2 = nc2;
    }
    if (lane == 0) {
        ssamp[0][2 * w] = i1; ssamp[0][2 * w + 1] = i2;
        ssamp[1][2 * w] = c1; ssamp[1][2 * w + 1] = c2;
    }
    __syncthreads();

    // threshold: 10th best of 16 samples (ties via lane)
    if (w < 2) {
        float v = (lane < 16) ? ssamp[w][lane] : (w ? 3.0e38f : -1.f);
        int cnt = 0;
        #pragma unroll
        for (int j = 0; j < 16; j++) {
            float o = __shfl_sync(FULLM, v, j);
            bool better = (w == 0) ? (o > v) : (o < v);
            cnt += (better || (o == v && j < lane)) ? 1 : 0;
        }
        unsigned sel = __ballot_sync(FULLM, lane < 16 && cnt == 9);
        int l = __ffs(sel) - 1;
        float T = __shfl_sync(FULLM, v, l);
        if (lane == 0) sT[w] = T;
    }
    __syncthreads();
    float Ti = sT[0], Tc = sT[1];

    // phase B: compaction
    for (int n = n0 + tid * 4; n < nfull; n += TPB * 4) {
        float4 v0 = *reinterpret_cast<const float4*>(col + n);
        float4 v1 = *reinterpret_cast<const float4*>(col + n + 2);
        unsigned wv = g_valid[n >> 5] >> (n & 31);
        float io[4] = { (wv & 1u) ? v0.x : 0.f, (wv & 2u) ? v0.z : 0.f,
                        (wv & 4u) ? v1.x : 0.f, (wv & 8u) ? v1.z : 0.f };
        float co[4] = { (wv & 1u) ? v0.y : BIG_F, (wv & 2u) ? v0.w : BIG_F,
                        (wv & 4u) ? v1.y : BIG_F, (wv & 8u) ? v1.w : BIG_F };
        #pragma unroll
        for (int k = 0; k < 4; k++) {
            int ni = n + k;
            if (io[k] >= Ti) {
                ull key = ((ull)(unsigned)~fkey(io[k]) << 32) | (unsigned)ni;
                int p = atomicAdd(&scnt[0], 1); if (p < CAP) sbuf[0][p] = key;
            }
            if (co[k] <= Tc) {
                ull key = ((ull)fkey(co[k]) << 32) | (unsigned)ni;
                int p = atomicAdd(&scnt[1], 1); if (p < CAP) sbuf[1][p] = key;
            }
        }
    }
    for (int n = nfull + tid; n < n1; n += TPB) {
        float2 p = col[n];
        bool vd = (g_valid[n >> 5] >> (n & 31)) & 1u;
        float io = vd ? p.x : 0.f;
        float co = vd ? p.y : BIG_F;
        if (io >= Ti) {
            ull key = ((ull)(unsigned)~fkey(io) << 32) | (unsigned)n;
            int q = atomicAdd(&scnt[0], 1); if (q < CAP) sbuf[0][q] = key;
        }
        if (co <= Tc) {
            ull key = ((ull)fkey(co) << 32) | (unsigned)n;
            int q = atomicAdd(&scnt[1], 1); if (q < CAP) sbuf[1][q] = key;
        }
    }
    __syncthreads();

    // exact top-10 extraction from buffers
    if (w < 2) {
        int cnt = min(scnt[w], CAP);
        ull* buf = sbuf[w];
        for (int r = 0; r < TK; r++) {
            ull m = ~0ULL;
            for (int i = lane; i < cnt; i += 32) m = umin64(m, buf[i]);
            #pragma unroll
            for (int off = 16; off; off >>= 1)
                m = umin64(m, __shfl_xor_sync(FULLM, m, off));
            for (int i = lane; i < cnt; i += 32)
                if (buf[i] == m) buf[i] = ~0ULL;
            if (lane == 0) skeep[w][r] = m;
        }
    }
    __syncthreads();
    if (w == 0 && lane < TK) g_piou [(g * SPLIT + s) * TK + lane] = skeep[0][lane];
    if (w == 1 && lane < TK) g_pcost[(g * SPLIT + s) * TK + lane] = skeep[1][lane];
    __syncthreads();
    if (tid == 0) {
        __threadfence();
        int old = atomicAdd(&g_done[g], 1);
        sfl = (old == (int)gridDim.y - 1);
    }
    __syncthreads();
    if (!sfl) return;

    // last block for g: merge 80 keys per list
    if (w < 2) {
        const ull* src = (w == 0) ? &g_piou[g * TOTK] : &g_pcost[g * TOTK];
        ull k0 = (lane      < TOTK) ? __ldcg(&src[lane])      : ~0ULL;
        ull k1 = (lane + 32 < TOTK) ? __ldcg(&src[lane + 32]) : ~0ULL;
        ull k2 = (lane + 64 < TOTK) ? __ldcg(&src[lane + 64]) : ~0ULL;
        for (int r = 0; r < TK; r++) {
            ull m = umin64(k0, umin64(k1, k2));
            #pragma unroll
            for (int off = 16; off; off >>= 1)
                m = umin64(m, __shfl_xor_sync(FULLM, m, off));
            if (k0 == m) k0 = ~0ULL;
            else if (k1 == m) k1 = ~0ULL;
            else if (k2 == m) k2 = ~0ULL;
            if (lane == 0) skeep[w][r] = m;
        }
    }
    __syncthreads();
    if (tid == 0) {
        float ssum = 0.f;
        #pragma unroll
        for (int r = 0; r < TK; r++) {
            ull k = skeep[0][r];
            if (k != ~0ULL) ssum += unfkey(~(unsigned)(k >> 32));
        }
        int dk = (int)ssum;
        sdk = dk < 1 ? 1 : (dk > TK ? TK : dk);
    }
    __syncthreads();
    if (tid < sdk) {
        ull k = skeep[1][tid];
        if (k != ~0ULL) {
            int n = (int)(unsigned)k;
            atomicAdd(&g_cnt[n], 1);
            atomicMin(&g_mg[n], g);
        }
    }
}

// -------- finalize: no row scan; uses precomputed row argmin --------
__global__ void kFinal(float* __restrict__ out, int N, int G) {
    int n = blockIdx.x * blockDim.x + threadIdx.x;
    if (n >= N) return;
    int c = g_cnt[n];
    bool val = (g_valid[n >> 5] >> (n & 31)) & 1u;
    float gi = 0.f, lb = -1.f, io = -INF_F;
    if (c == 1) {
        int g = g_mg[n];
        gi = (float)g; lb = 1.f;
        io = val ? G_IC[g * N + n].x : 0.f;
    } else if (c > 1) {
        lb = 1.f;
        if (!val) { gi = 0.f; io = 0.f; }
        else {
            int bg = (int)(unsigned)g_amin[n];
            gi = (float)bg;
            io = G_IC[bg * N + n].x;
        }
    }
    out[n] = gi;
    out[N + n] = lb;
    out[2 * N + n] = io;
}

extern "C" void kernel_launch(void* const* d_in, const int* in_sizes, int n_in,
                              void* d_out, int out_size) {
    const float* ps  = (const float*)d_in[0];
    const float* pri = (const float*)d_in[1];
    const float* dec = (const float*)d_in[2];
    const float* gtb = (const float*)d_in[3];
    const int*   gtl = (const int*)d_in[4];
    int N = in_sizes[1] / 4;
    int G = in_sizes[3] / 4;
    int C = in_sizes[0] / N;
    if (N > NMAX || G > GMAX || C > CMAX) return;
    float* out = (float*)d_out;
    (void)out_size; (void)n_in;

    if (C == 80) {
        kAB<<<(N + 127) / 128, 256>>>(ps, pri, dec, gtb, gtl, N, G);
    } else {
        kSetup<<<(N + TPB - 1) / TPB, TPB>>>(N, G);
        kAgen<<<(N + TPB - 1) / TPB, TPB>>>(ps, N, C);
        dim3 gb((N + TPB - 1) / TPB, (G + GTILE - 1) / GTILE);
        kB<<<gb, TPB>>>(pri, dec, gtb, gtl, N, G);
    }
    dim3 gt(G, SPLIT);
    kTopPart<<<gt, TPB>>>(N);
    kFinal<<<(N + TPB - 1) / TPB, TPB>>>(out, N, G);
}

// round 17
// speedup vs baseline: 1.0557x; 1.0009x over previous
#include <cuda_runtime.h>
#include <stdint.h>

#define NMAX 33600
#define GMAX 128
#define CMAX 80
#define TPB 256
#define TK 10
#define GTILE 16
#define SPLIT 8
#define NW (TPB / 32)
#define CAP 768
#define TOTK (SPLIT * TK)               // 80 partial keys per gt per list
#define EPSF 1e-7f
#define INF_F 100000.0f
#define BIG_F 100000000.0f
#define CRAD 2.5f
#define NWORDS ((NMAX + 31) / 32)
#define FULLM 0xffffffffu

typedef unsigned long long ull;

// ---- scratch as __device__ globals (allocation-free rule) ----
__device__ float    g_D[(size_t)CMAX * NMAX];    // fallback path only
__device__ float    g_sumL1[NMAX];               // fallback path only
__device__ float4   g_ic4[(size_t)GMAX * NMAX / 2];   // {iou,cost} pairs, 16B-aligned
#define G_IC ((float2*)g_ic4)
__device__ unsigned g_valid[NWORDS];
__device__ int      g_cnt[NMAX];
__device__ int      g_mg[NMAX];
__device__ ull      g_amin[NMAX];                // row argmin: (fkey(cost)<<32)|g
__device__ int      g_done[GMAX];
__device__ ull      g_piou [GMAX * TOTK];
__device__ ull      g_pcost[GMAX * TOTK];

// monotone float->uint (ascending order preserved)
__device__ __forceinline__ unsigned fkey(float f) {
    unsigned u = __float_as_uint(f);
    return (u & 0x80000000u) ? ~u : (u | 0x80000000u);
}
__device__ __forceinline__ float unfkey(unsigned k) {
    unsigned u = (k & 0x80000000u) ? (k ^ 0x80000000u) : ~k;
    return __uint_as_float(u);
}

__device__ __forceinline__ ull umin64(ull a, ull b) { return a < b ? a : b; }

// ============ kAB: fully fused logits + pairwise (C==80 fast path) ==========
// Block = 256 threads, 128 anchors. Thread (a = tid&127, h = tid>>7) covers
// anchor a x GT-half h. Logit matrix lives in smem; g_D never touched.
// g_amin and g_valid are plain stores (full row visible in-block).
// Per-pair argmin uses strict float compare (g ascending => first-min);
// 64-bit key built once per thread at the end.
__global__ void __launch_bounds__(256) kAB(
    const float* __restrict__ ps, const float* __restrict__ priors,
    const float* __restrict__ dec, const float* __restrict__ gtb,
    const int* __restrict__ gtl, int N, int G)
{
    __shared__ float    sD[80 * 129];     // [c][a], stride 129 (conflict-free)
    __shared__ float    sPart[2 * 128];   // per-half partial sumL1
    __shared__ float4   sg0[GMAX];
    __shared__ float4   sg1[GMAX];
    __shared__ ull      skm[256];
    __shared__ unsigned sb[8];

    int tid = threadIdx.x;
    int n0 = blockIdx.x * 128;
    int rows = min(128, N - n0);

    // fused setup
    if (tid < rows) { g_cnt[n0 + tid] = 0; g_mg[n0 + tid] = 0x7fffffff; }
    if (blockIdx.x == 0 && tid < GMAX) g_done[tid] = 0;

    // gt descriptors (label pre-scaled by smem row stride 129)
    if (tid < G) {
        int g = tid;
        float x0 = gtb[4*g+0], y0 = gtb[4*g+1], x1 = gtb[4*g+2], y1 = gtb[4*g+3];
        sg0[g] = make_float4(x0, y0, x1, y1);
        float gcx = (x0 + x1) * 0.5f, gcy = (y0 + y1) * 0.5f;
        float area = fmaxf(x1 - x0, 0.f) * fmaxf(y1 - y0, 0.f);
        sg1[g] = make_float4(gcx, gcy, area, __int_as_float(gtl[g] * 129));
    }

    // stage ps coalesced into sD (as raw p)
    for (int i = tid; i < rows * 80; i += 256) {
        int a = i / 80, c = i - a * 80;
        sD[c * 129 + a] = ps[n0 * 80 + i];
    }
    __syncthreads();

    int a = tid & 127, h = tid >> 7;

    // phase 1: logits in place + grouped-product partial sumL1 (8 groups of 5)
    if (a < rows) {
        float gl = 0.f;
        #pragma unroll
        for (int k2 = 0; k2 < 8; k2++) {
            float prod = 1.f;
            #pragma unroll
            for (int m = 0; m < 5; m++) {
                int c = h * 40 + k2 * 5 + m;
                float p = sD[c * 129 + a];
                float q = 1.f - p;
                prod *= q;
                sD[c * 129 + a] = __logf(__fdividef(p, q));
            }
            gl += __logf(prod);
        }
        sPart[h * 128 + a] = gl;
    }
    __syncthreads();

    // phase 2: pairwise over this thread's GT half
    int n = n0 + a;
    bool vacc = false;
    float bestc = 3.4e38f;
    int   bestg = 0;
    int half = (G + 1) >> 1;
    int gs = h * half;
    int ge = min(G, gs + half);
    if (a < rows) {
        float4 pq = ((const float4*)priors)[n];
        float px = pq.x, py = pq.y;
        float a1 = px + CRAD * pq.z, a2 = px - CRAD * pq.z;
        float b1 = py + CRAD * pq.w, b2 = py - CRAD * pq.w;
        float4 dq = ((const float4*)dec)[n];
        float dx0 = dq.x, dy0 = dq.y, dx1 = dq.z, dy1 = dq.w;
        float aa = fmaxf(dx1 - dx0, 0.f) * fmaxf(dy1 - dy0, 0.f);
        float sL1 = sPart[a] + sPart[128 + a];
        int base = gs * N + n;
        #pragma unroll 4
        for (int g = gs; g < ge; g++) {
            float4 q0 = sg0[g];
            float4 q1 = sg1[g];
            float m1 = fminf(fminf(px - q0.x, py - q0.y), fminf(q0.z - px, q0.w - py));
            float m2 = fminf(fminf(a1 - q1.x, b1 - q1.y), fminf(q1.x - a2, q1.y - b2));
            bool ing = m1 > 0.f, inc = m2 > 0.f;
            vacc = vacc || ing || inc;
            float w = fmaxf(fminf(dx1, q0.z) - fmaxf(dx0, q0.x), 0.f);
            float hh = fmaxf(fminf(dy1, q0.w) - fmaxf(dy0, q0.y), 0.f);
            float inter = w * hh;
            float uni = fmaxf(aa + q1.z - inter, EPSF);
            float iou = __fdividef(inter, uni);
            float cls = -sD[__float_as_int(q1.w) + a] - sL1;
            float cost = cls - 3.0f * __logf(iou + EPSF);
            if (!(ing && inc)) cost += INF_F;
            G_IC[base] = make_float2(iou, cost);
            base += N;
            if (cost < bestc) { bestc = cost; bestg = g; }   // g ascending => first-min
        }
    }
    skm[tid] = (a < rows) ? (((ull)fkey(bestc) << 32) | (unsigned)bestg) : ~0ULL;
    unsigned bal = __ballot_sync(FULLM, vacc);
    if ((tid & 31) == 0) sb[tid >> 5] = bal;
    __syncthreads();
    if (tid < 128 && tid < rows)
        g_amin[n0 + tid] = umin64(skm[tid], skm[tid + 128]);
    if (tid < 4 && tid * 32 < rows)
        g_valid[(n0 >> 5) + tid] = sb[tid] | sb[tid + 4];
}

// -------- generic fallbacks (C != 80; not used for this problem's shapes) ----
__global__ void kSetup(int N, int G) {
    int i = blockIdx.x * blockDim.x + threadIdx.x;
    if (i < N) { g_cnt[i] = 0; g_mg[i] = 0x7fffffff; g_amin[i] = ~0ULL; }
    if (i < NWORDS) g_valid[i] = 0u;
    if (i < GMAX) g_done[i] = 0;
}
__global__ void kAgen(const float* __restrict__ ps, int N, int C) {
    int n = blockIdx.x * blockDim.x + threadIdx.x;
    if (n >= N) return;
    float ssum = 0.f;
    for (int c = 0; c < C; c++) {
        float p = ps[(size_t)n * C + c];
        float L  = fmaxf(__logf(p), -100.f);
        float L1 = fmaxf(__logf(1.f - p), -100.f);
        g_D[c * N + n] = L - L1;
        ssum += L1;
    }
    g_sumL1[n] = ssum;
}
__global__ void __launch_bounds__(TPB) kB(
    const float* __restrict__ priors, const float* __restrict__ dec,
    const float* __restrict__ gtb, const int* __restrict__ gtl,
    int N, int G)
{
    __shared__ float4 sg0[GTILE];
    __shared__ float4 sg1[GTILE];
    int tid = threadIdx.x;
    int g0 = blockIdx.y * GTILE;
    int gcnt = min(GTILE, G - g0);
    if (tid < gcnt) {
        int g = g0 + tid;
        float x0 = gtb[4*g+0], y0 = gtb[4*g+1], x1 = gtb[4*g+2], y1 = gtb[4*g+3];
        sg0[tid] = make_float4(x0, y0, x1, y1);
        float gcx = (x0 + x1) * 0.5f, gcy = (y0 + y1) * 0.5f;
        float area = fmaxf(x1 - x0, 0.f) * fmaxf(y1 - y0, 0.f);
        sg1[tid] = make_float4(gcx, gcy, area, __int_as_float(gtl[g] * N));
    }
    __syncthreads();

    int n = blockIdx.x * blockDim.x + tid;
    if (n >= N) return;
    float4 pq = ((const float4*)priors)[n];
    float px = pq.x, py = pq.y;
    float a1 = px + CRAD * pq.z, a2 = px - CRAD * pq.z;
    float b1 = py + CRAD * pq.w, b2 = py - CRAD * pq.w;
    float4 dq = ((const float4*)dec)[n];
    float dx0 = dq.x, dy0 = dq.y, dx1 = dq.z, dy1 = dq.w;
    float aa = fmaxf(dx1 - dx0, 0.f) * fmaxf(dy1 - dy0, 0.f);
    float sL1 = g_sumL1[n];

    bool vacc = false;
    ull kmin = ~0ULL;
    int base = g0 * N + n;
    for (int gi = 0; gi < gcnt; gi++) {
        float4 q0 = sg0[gi];
        float4 q1 = sg1[gi];
        float m1 = fminf(fminf(px - q0.x, py - q0.y), fminf(q0.z - px, q0.w - py));
        float m2 = fminf(fminf(a1 - q1.x, b1 - q1.y), fminf(q1.x - a2, q1.y - b2));
        bool ing = m1 > 0.f, inc = m2 > 0.f;
        vacc = vacc || ing || inc;
        float w = fmaxf(fminf(dx1, q0.z) - fmaxf(dx0, q0.x), 0.f);
        float h = fmaxf(fminf(dy1, q0.w) - fmaxf(dy0, q0.y), 0.f);
        float inter = w * h;
        float uni = fmaxf(aa + q1.z - inter, EPSF);
        float iou = __fdividef(inter, uni);
        float cls = -g_D[__float_as_int(q1.w) + n] - sL1;
        float cost = cls - 3.0f * __logf(iou + EPSF);
        if (!(ing && inc)) cost += INF_F;
        G_IC[base] = make_float2(iou, cost);
        base += N;
        ull key = ((ull)fkey(cost) << 32) | (unsigned)(g0 + gi);
        kmin = umin64(kmin, key);
    }
    atomicMin(&g_amin[n], kmin);
    unsigned m = __ballot_sync(__activemask(), vacc);
    if ((tid & 31) == 0 && m) atomicOr(&g_valid[n >> 5], m);
}

// -------- kTopPart: grid (G, SPLIT). float-threshold sampling + compaction.
//          Last block per g merges + dynamic_k + atomics. (measured-best) ----
__global__ void __launch_bounds__(TPB) kTopPart(int N) {
    __shared__ ull   sbuf[2][CAP];
    __shared__ float ssamp[2][16];
    __shared__ float sT[2];
    __shared__ int   scnt[2];
    __shared__ ull   skeep[2][TK];
    __shared__ int   sfl, sdk;

    int g = blockIdx.x, s = blockIdx.y;
    int tid = threadIdx.x, lane = tid & 31, w = tid >> 5;
    int len = (((N + SPLIT - 1) / SPLIT) + 3) & ~3;
    int n0 = s * len;
    int n1 = min(N, n0 + len);
    const float2* col = G_IC + g * N;

    if (tid < 2) scnt[tid] = 0;

    // phase A: per-thread float top-2, vectorized full scan
    float i1 = -1.f, i2 = -1.f;
    float c1 = 3.0e38f, c2 = 3.0e38f;
    int nfull = n0 + (((n1 - n0) / 4) * 4);
    for (int n = n0 + tid * 4; n < nfull; n += TPB * 4) {
        float4 v0 = *reinterpret_cast<const float4*>(col + n);
        float4 v1 = *reinterpret_cast<const float4*>(col + n + 2);
        unsigned wv = g_valid[n >> 5] >> (n & 31);
        float io[4] = { (wv & 1u) ? v0.x : 0.f, (wv & 2u) ? v0.z : 0.f,
                        (wv & 4u) ? v1.x : 0.f, (wv & 8u) ? v1.z : 0.f };
        float co[4] = { (wv & 1u) ? v0.y : BIG_F, (wv & 2u) ? v0.w : BIG_F,
                        (wv & 4u) ? v1.y : BIG_F, (wv & 8u) ? v1.w : BIG_F };
        #pragma unroll
        for (int k = 0; k < 4; k++) {
            if (io[k] > i2) { if (io[k] > i1) { i2 = i1; i1 = io[k]; } else i2 = io[k]; }
            if (co[k] < c2) { if (co[k] < c1) { c2 = c1; c1 = co[k]; } else c2 = co[k]; }
        }
    }
    for (int n = nfull + tid; n < n1; n += TPB) {
        float2 p = col[n];
        bool vd = (g_valid[n >> 5] >> (n & 31)) & 1u;
        float io = vd ? p.x : 0.f;
        float co = vd ? p.y : BIG_F;
        if (io > i2) { if (io > i1) { i2 = i1; i1 = io; } else i2 = io; }
        if (co < c2) { if (co < c1) { c2 = c1; c1 = co; } else c2 = co; }
    }
    #pragma unroll
    for (int off = 16; off; off >>= 1) {
        float oi1 = __shfl_xor_sync(FULLM, i1, off);
        float oi2 = __shfl_xor_sync(FULLM, i2, off);
        float ni1 = fmaxf(i1, oi1);
        float ni2 = fmaxf(fminf(i1, oi1), fmaxf(i2, oi2));
        i1 = ni1; i2 = ni2;
        float oc1 = __shfl_xor_sync(FULLM, c1, off);
        float oc2 = __shfl_xor_sync(FULLM, c2, off);
        float nc1 = fminf(c1, oc1);
        float nc2 = fminf(fmaxf(c1, oc1), fminf(c2, oc2));
        c1 = nc1; c2 = nc2;
    }
    if (lane == 0) {
        ssamp[0][2 * w] = i1; ssamp[0][2 * w + 1] = i2;
        ssamp[1][2 * w] = c1; ssamp[1][2 * w + 1] = c2;
    }
    __syncthreads();

    // threshold: 10th best of 16 samples (ties via lane)
    if (w < 2) {
        float v = (lane < 16) ? ssamp[w][lane] : (w ? 3.0e38f : -1.f);
        int cnt = 0;
        #pragma unroll
        for (int j = 0; j < 16; j++) {
            float o = __shfl_sync(FULLM, v, j);
            bool better = (w == 0) ? (o > v) : (o < v);
            cnt += (better || (o == v && j < lane)) ? 1 : 0;
        }
        unsigned sel = __ballot_sync(FULLM, lane < 16 && cnt == 9);
        int l = __ffs(sel) - 1;
        float T = __shfl_sync(FULLM, v, l);
        if (lane == 0) sT[w] = T;
    }
    __syncthreads();
    float Ti = sT[0], Tc = sT[1];

    // phase B: compaction
    for (int n = n0 + tid * 4; n < nfull; n += TPB * 4) {
        float4 v0 = *reinterpret_cast<const float4*>(col + n);
        float4 v1 = *reinterpret_cast<const float4*>(col + n + 2);
        unsigned wv = g_valid[n >> 5] >> (n & 31);
        float io[4] = { (wv & 1u) ? v0.x : 0.f, (wv & 2u) ? v0.z : 0.f,
                        (wv & 4u) ? v1.x : 0.f, (wv & 8u) ? v1.z : 0.f };
        float co[4] = { (wv & 1u) ? v0.y : BIG_F, (wv & 2u) ? v0.w : BIG_F,
                        (wv & 4u) ? v1.y : BIG_F, (wv & 8u) ? v1.w : BIG_F };
        #pragma unroll
        for (int k = 0; k < 4; k++) {
            int ni = n + k;
            if (io[k] >= Ti) {
                ull key = ((ull)(unsigned)~fkey(io[k]) << 32) | (unsigned)ni;
                int p = atomicAdd(&scnt[0], 1); if (p < CAP) sbuf[0][p] = key;
            }
            if (co[k] <= Tc) {
                ull key = ((ull)fkey(co[k]) << 32) | (unsigned)ni;
                int p = atomicAdd(&scnt[1], 1); if (p < CAP) sbuf[1][p] = key;
            }
        }
    }
    for (int n = nfull + tid; n < n1; n += TPB) {
        float2 p = col[n];
        bool vd = (g_valid[n >> 5] >> (n & 31)) & 1u;
        float io = vd ? p.x : 0.f;
        float co = vd ? p.y : BIG_F;
        if (io >= Ti) {
            ull key = ((ull)(unsigned)~fkey(io) << 32) | (unsigned)n;
            int q = atomicAdd(&scnt[0], 1); if (q < CAP) sbuf[0][q] = key;
        }
        if (co <= Tc) {
            ull key = ((ull)fkey(co) << 32) | (unsigned)n;
            int q = atomicAdd(&scnt[1], 1); if (q < CAP) sbuf[1][q] = key;
        }
    }
    __syncthreads();

    // exact top-10 extraction from buffers
    if (w < 2) {
        int cnt = min(scnt[w], CAP);
        ull* buf = sbuf[w];
        for (int r = 0; r < TK; r++) {
            ull m = ~0ULL;
            for (int i = lane; i < cnt; i += 32) m = umin64(m, buf[i]);
            #pragma unroll
            for (int off = 16; off; off >>= 1)
                m = umin64(m, __shfl_xor_sync(FULLM, m, off));
            for (int i = lane; i < cnt; i += 32)
                if (buf[i] == m) buf[i] = ~0ULL;
            if (lane == 0) skeep[w][r] = m;
        }
    }
    __syncthreads();
    if (w == 0 && lane < TK) g_piou [(g * SPLIT + s) * TK + lane] = skeep[0][lane];
    if (w == 1 && lane < TK) g_pcost[(g * SPLIT + s) * TK + lane] = skeep[1][lane];
    __syncthreads();
    if (tid == 0) {
        __threadfence();
        int old = atomicAdd(&g_done[g], 1);
        sfl = (old == (int)gridDim.y - 1);
    }
    __syncthreads();
    if (!sfl) return;

    // last block for g: merge 80 keys per list
    if (w < 2) {
        const ull* src = (w == 0) ? &g_piou[g * TOTK] : &g_pcost[g * TOTK];
        ull k0 = (lane      < TOTK) ? __ldcg(&src[lane])      : ~0ULL;
        ull k1 = (lane + 32 < TOTK) ? __ldcg(&src[lane + 32]) : ~0ULL;
        ull k2 = (lane + 64 < TOTK) ? __ldcg(&src[lane + 64]) : ~0ULL;
        for (int r = 0; r < TK; r++) {
            ull m = umin64(k0, umin64(k1, k2));
            #pragma unroll
            for (int off = 16; off; off >>= 1)
                m = umin64(m, __shfl_xor_sync(FULLM, m, off));
            if (k0 == m) k0 = ~0ULL;
            else if (k1 == m) k1 = ~0ULL;
            else if (k2 == m) k2 = ~0ULL;
            if (lane == 0) skeep[w][r] = m;
        }
    }
    __syncthreads();
    if (tid == 0) {
        float ssum = 0.f;
        #pragma unroll
        for (int r = 0; r < TK; r++) {
            ull k = skeep[0][r];
            if (k != ~0ULL) ssum += unfkey(~(unsigned)(k >> 32));
        }
        int dk = (int)ssum;
        sdk = dk < 1 ? 1 : (dk > TK ? TK : dk);
    }
    __syncthreads();
    if (tid < sdk) {
        ull k = skeep[1][tid];
        if (k != ~0ULL) {
            int n = (int)(unsigned)k;
            atomicAdd(&g_cnt[n], 1);
            atomicMin(&g_mg[n], g);
        }
    }
}

// -------- finalize: no row scan; uses precomputed row argmin --------
__global__ void kFinal(float* __restrict__ out, int N, int G) {
    int n = blockIdx.x * blockDim.x + threadIdx.x;
    if (n >= N) return;
    int c = g_cnt[n];
    bool val = (g_valid[n >> 5] >> (n & 31)) & 1u;
    float gi = 0.f, lb = -1.f, io = -INF_F;
    if (c == 1) {
        int g = g_mg[n];
        gi = (float)g; lb = 1.f;
        io = val ? G_IC[g * N + n].x : 0.f;
    } else if (c > 1) {
        lb = 1.f;
        if (!val) { gi = 0.f; io = 0.f; }
        else {
            int bg = (int)(unsigned)g_amin[n];
            gi = (float)bg;
            io = G_IC[bg * N + n].x;
        }
    }
    out[n] = gi;
    out[N + n] = lb;
    out[2 * N + n] = io;
}

extern "C" void kernel_launch(void* const* d_in, const int* in_sizes, int n_in,
                              void* d_out, int out_size) {
    const float* ps  = (const float*)d_in[0];
    const float* pri = (const float*)d_in[1];
    const float* dec = (const float*)d_in[2];
    const float* gtb = (const float*)d_in[3];
    const int*   gtl = (const int*)d_in[4];
    int N = in_sizes[1] / 4;
    int G = in_sizes[3] / 4;
    int C = in_sizes[0] / N;
    if (N > NMAX || G > GMAX || C > CMAX) return;
    float* out = (float*)d_out;
    (void)out_size; (void)n_in;

    if (C == 80) {
        kAB<<<(N + 127) / 128, 256>>>(ps, pri, dec, gtb, gtl, N, G);
    } else {
        kSetup<<<(N + TPB - 1) / TPB, TPB>>>(N, G);
        kAgen<<<(N + TPB - 1) / TPB, TPB>>>(ps, N, C);
        dim3 gb((N + TPB - 1) / TPB, (G + GTILE - 1) / GTILE);
        kB<<<gb, TPB>>>(pri, dec, gtb, gtl, N, G);
    }
    dim3 gt(G, SPLIT);
    kTopPart<<<gt, TPB>>>(N);
    kFinal<<<(N + TPB - 1) / TPB, TPB>>>(out, N, G);
}